// round 16
// baseline (speedup 1.0000x reference)
#include <cuda_runtime.h>
#include <cuda_fp16.h>
#include <math.h>

#define NB   512
#define NC   112
#define NP   64
#define NHW  256
#define NOC  256
#define NT   512    // 16 warps

typedef unsigned long long u64;
typedef unsigned int u32;

__device__ __forceinline__ u32 saddr(const void* p) {
    return (u32)__cvta_generic_to_shared(p);
}

// ---- shared layout (float index). total 52800 floats = 211200 B ----
// Overlays (lifetime-disjoint):
//   PWT region: z fp16 A-operand (staging+corr) -> pwt fp16 (GEMM passes)
//   FT  region: search fp16 B-operand (staging+corr) -> ft fp16 (GEMM/tap)
//   CORR region: corr fp32 (corr..dw) -> P partials (tap..epilogue)
#define SM_BNSC 0       // 256
#define SM_BNSH 256     // 256
#define SM_ATT  512     // 64
#define SM_H    576     // 64
#define SM_A    640     // 64
#define SM_DWW  704     // 576
#define SM_WP   1344    // 5120 (A_tap fp16 [48][68 u32] box / [16][68] cls)
#define SM_DW   6464    // 8448 = dw fp16 [64][132 u32] (528B rows)
#define SM_PWT  14912   // 4608 = pwt fp16 [128][36 u32] | z fp16 [64][120h]
#define SM_FT   19520   // 16896 = ft fp16 [128][132 u32] | search fp16 [112][132 u32]
#define SM_CORR 36416   // 16384 = corr fp32 [64][256] | P f32 [48][256]
#define SM_TOT  52800

// pointwise GEMM pass via mma.sync: 128o x 256px, K=64, fp16 in, fp32 acc
__device__ __forceinline__ void gemm_mma(float* sm, int lane, int warp, int o_base)
{
    const u32 pwt_b = saddr(sm + SM_PWT);
    const u32 dw_b  = saddr(sm + SM_DW);
    u32* s_ft = (u32*)(sm + SM_FT);
    const float* s_bnsc = sm + SM_BNSC;
    const float* s_bnsh = sm + SM_BNSH;

    const int mt = warp >> 1, h = warp & 1;
    const int m0 = mt * 16;
    const int g  = lane >> 2, t4 = lane & 3;

    u32 A[4][4];
    {
        const u32 aoff = pwt_b
            + (u32)(m0 + (lane & 7) + ((lane >> 3) & 1) * 8) * 144u
            + (u32)((lane >> 4) & 1) * 16u;
#pragma unroll
        for (int ks = 0; ks < 4; ks++) {
            asm volatile("ldmatrix.sync.aligned.m8n8.x4.shared.b16 {%0,%1,%2,%3}, [%4];"
                : "=r"(A[ks][0]), "=r"(A[ks][1]), "=r"(A[ks][2]), "=r"(A[ks][3])
                : "r"(aoff + (u32)ks * 32u));
        }
    }

    const float sc0 = s_bnsc[o_base + m0 + g],     sh0 = s_bnsh[o_base + m0 + g];
    const float sc1 = s_bnsc[o_base + m0 + g + 8], sh1 = s_bnsh[o_base + m0 + g + 8];
    const u32 boff = dw_b + (u32)(lane & 15) * 528u + (u32)h * 256u;

#pragma unroll 4
    for (int nt = 0; nt < 16; nt++) {
        float c0 = 0.f, c1 = 0.f, c2 = 0.f, c3 = 0.f;
#pragma unroll
        for (int ks = 0; ks < 4; ks++) {
            u32 b0, b1;
            asm volatile("ldmatrix.sync.aligned.m8n8.x2.trans.shared.b16 {%0,%1}, [%2];"
                : "=r"(b0), "=r"(b1)
                : "r"(boff + (u32)ks * 8448u + (u32)nt * 16u));
            asm volatile(
                "mma.sync.aligned.m16n8k16.row.col.f32.f16.f16.f32 "
                "{%0,%1,%2,%3}, {%4,%5,%6,%7}, {%8,%9}, {%0,%1,%2,%3};"
                : "+f"(c0), "+f"(c1), "+f"(c2), "+f"(c3)
                : "r"(A[ks][0]), "r"(A[ks][1]), "r"(A[ks][2]), "r"(A[ks][3]),
                  "r"(b0), "r"(b1));
        }
        c0 = fmaxf(fmaf(c0, sc0, sh0), 0.0f);
        c1 = fmaxf(fmaf(c1, sc0, sh0), 0.0f);
        c2 = fmaxf(fmaf(c2, sc1, sh1), 0.0f);
        c3 = fmaxf(fmaf(c3, sc1, sh1), 0.0f);
        __half2 p01 = __floats2half2_rn(c0, c1);
        __half2 p23 = __floats2half2_rn(c2, c3);
        const int n0h = h * 64 + nt * 4;
        s_ft[(m0 + g)     * 132 + n0h + t4] = *(u32*)&p01;
        s_ft[(m0 + g + 8) * 132 + n0h + t4] = *(u32*)&p23;
    }
}

// tap GEMM: P[m0+g / +8][col] (+)= sum_c A_tap[r][c] * ft[c][px]
template<int NT_I>
__device__ __forceinline__ void tap_mma(float* sm, int lane, int mt, int nq,
                                        float* P, bool accum)
{
    const int m0 = mt * 16;
    const int g = lane >> 2, t4 = lane & 3;
    const u32 aoff = saddr(sm + SM_WP)
        + (u32)(m0 + (lane & 15)) * 272u
        + (u32)((lane >> 4) & 1) * 16u;
    const u32 boff = saddr(sm + SM_FT)
        + (u32)(lane & 15) * 528u + (u32)(nq * NT_I * 16);

    float acc[NT_I][4];
#pragma unroll
    for (int nt = 0; nt < NT_I; nt++)
#pragma unroll
        for (int e = 0; e < 4; e++) acc[nt][e] = 0.f;

#pragma unroll
    for (int ks = 0; ks < 8; ks++) {
        u32 A0, A1, A2, A3;
        asm volatile("ldmatrix.sync.aligned.m8n8.x4.shared.b16 {%0,%1,%2,%3}, [%4];"
            : "=r"(A0), "=r"(A1), "=r"(A2), "=r"(A3)
            : "r"(aoff + (u32)ks * 32u));
#pragma unroll
        for (int nt = 0; nt < NT_I; nt++) {
            u32 b0, b1;
            asm volatile("ldmatrix.sync.aligned.m8n8.x2.trans.shared.b16 {%0,%1}, [%2];"
                : "=r"(b0), "=r"(b1)
                : "r"(boff + (u32)ks * 8448u + (u32)nt * 16u));
            asm volatile(
                "mma.sync.aligned.m16n8k16.row.col.f32.f16.f16.f32 "
                "{%0,%1,%2,%3}, {%4,%5,%6,%7}, {%8,%9}, {%0,%1,%2,%3};"
                : "+f"(acc[nt][0]), "+f"(acc[nt][1]),
                  "+f"(acc[nt][2]), "+f"(acc[nt][3])
                : "r"(A0), "r"(A1), "r"(A2), "r"(A3), "r"(b0), "r"(b1));
        }
    }

#pragma unroll
    for (int nt = 0; nt < NT_I; nt++) {
        const int col = nq * (NT_I * 8) + nt * 8 + 2 * t4;
        const int r0 = m0 + g, r1 = m0 + g + 8;
        if (!accum) {
            P[r0 * 256 + col]     = acc[nt][0];
            P[r0 * 256 + col + 1] = acc[nt][1];
            P[r1 * 256 + col]     = acc[nt][2];
            P[r1 * 256 + col + 1] = acc[nt][3];
        } else {
            P[r0 * 256 + col]     += acc[nt][0];
            P[r0 * 256 + col + 1] += acc[nt][1];
            P[r1 * 256 + col]     += acc[nt][2];
            P[r1 * 256 + col + 1] += acc[nt][3];
        }
    }
}

__global__ void __launch_bounds__(NT, 1)
btl_fused(
    const float* __restrict__ search, const float* __restrict__ kern,
    const float* __restrict__ ca_w1, const float* __restrict__ ca_b1,
    const float* __restrict__ ca_w2, const float* __restrict__ ca_b2,
    const float* __restrict__ cls_dw, const float* __restrict__ cls_pw,
    const float* __restrict__ cls_bng, const float* __restrict__ cls_bnb,
    const float* __restrict__ cls_bnm, const float* __restrict__ cls_bnv,
    const float* __restrict__ cls_predw, const float* __restrict__ cls_predb,
    const float* __restrict__ box_dw, const float* __restrict__ box_pw,
    const float* __restrict__ box_bng, const float* __restrict__ box_bnb,
    const float* __restrict__ box_bnm, const float* __restrict__ box_bnv,
    const float* __restrict__ box_predw, const float* __restrict__ box_predb,
    const float* __restrict__ adjust, const float* __restrict__ biasp,
    float* __restrict__ out)
{
    extern __shared__ float sm[];
    const int tid  = threadIdx.x;
    const int lane = tid & 31;
    const int warp = tid >> 5;
    const int s    = blockIdx.x >> 1;
    const int t    = blockIdx.x & 1;

    float* s_att  = sm + SM_ATT;
    float* s_h    = sm + SM_H;
    float* s_a    = sm + SM_A;
    float* s_corr = sm + SM_CORR;

    const float* gS = search + (size_t)s * NC * NHW;
    const float* gZ = kern   + (size_t)s * NC * NP;
    const float* dwW = t ? box_dw : cls_dw;
    const float* pwW = t ? box_pw : cls_pw;
    const float* predW = t ? box_predw : cls_predw;

    // ===== Phase A: stage search fp16 (B op, FT region), z fp16 (A op, PWT region) =====
    {
        u32* bd = (u32*)(sm + SM_FT);
        const float4* src = (const float4*)gS;
#pragma unroll
        for (int j = 0; j < 14; j++) {
            int i = tid + j * NT;            // 7168 float4s
            int c = i >> 6, col4 = i & 63;
            float4 v = src[i];
            __half2 h0 = __floats2half2_rn(v.x, v.y);
            __half2 h1 = __floats2half2_rn(v.z, v.w);
            bd[c * 132 + col4 * 2]     = *(u32*)&h0;
            bd[c * 132 + col4 * 2 + 1] = *(u32*)&h1;
        }
        __half* ad = (__half*)(sm + SM_PWT);
#pragma unroll
        for (int j = 0; j < 14; j++) {
            int i = tid + j * NT;            // 7168 halves
            int p = i & 63, c = i >> 6;
            ad[p * 120 + c] = __float2half_rn(gZ[c * 64 + p]);
        }
    }
    for (int i = tid; i < NP * 9; i += NT) sm[SM_DWW + i] = dwW[i];
    if (tid < NOC) {
        const float* bng = t ? box_bng : cls_bng;
        const float* bnb = t ? box_bnb : cls_bnb;
        const float* bnm = t ? box_bnm : cls_bnm;
        const float* bnv = t ? box_bnv : cls_bnv;
        float sc = bng[tid] * rsqrtf(bnv[tid] + 1e-5f);
        sm[SM_BNSC + tid] = sc;
        sm[SM_BNSH + tid] = bnb[tid] - bnm[tid] * sc;
    }
    __syncthreads();

    // ===== Phase B: corr mma 64p x 256px, K=112 (16 warps: 4 mt x 4 nq) =====
    {
        const int mt = warp >> 2, nq = warp & 3;
        const int m0 = mt * 16;
        const int g  = lane >> 2, t4 = lane & 3;

        u32 A[7][4];
        const u32 abase = saddr(sm + SM_PWT)
            + (u32)(m0 + (lane & 15)) * 240u + (u32)((lane >> 4) & 1) * 16u;
#pragma unroll
        for (int ks = 0; ks < 7; ks++) {
            asm volatile("ldmatrix.sync.aligned.m8n8.x4.shared.b16 {%0,%1,%2,%3}, [%4];"
                : "=r"(A[ks][0]), "=r"(A[ks][1]), "=r"(A[ks][2]), "=r"(A[ks][3])
                : "r"(abase + (u32)ks * 32u));
        }
        const u32 bbase = saddr(sm + SM_FT)
            + (u32)(lane & 15) * 528u + (u32)nq * 128u;
#pragma unroll
        for (int nt = 0; nt < 8; nt++) {
            float c0 = 0.f, c1 = 0.f, c2 = 0.f, c3 = 0.f;
#pragma unroll
            for (int ks = 0; ks < 7; ks++) {
                u32 b0, b1;
                asm volatile("ldmatrix.sync.aligned.m8n8.x2.trans.shared.b16 {%0,%1}, [%2];"
                    : "=r"(b0), "=r"(b1)
                    : "r"(bbase + (u32)ks * 8448u + (u32)nt * 16u));
                asm volatile(
                    "mma.sync.aligned.m16n8k16.row.col.f32.f16.f16.f32 "
                    "{%0,%1,%2,%3}, {%4,%5,%6,%7}, {%8,%9}, {%0,%1,%2,%3};"
                    : "+f"(c0), "+f"(c1), "+f"(c2), "+f"(c3)
                    : "r"(A[ks][0]), "r"(A[ks][1]), "r"(A[ks][2]), "r"(A[ks][3]),
                      "r"(b0), "r"(b1));
            }
            const int col = nq * 64 + nt * 8 + 2 * t4;
            s_corr[(m0 + g)     * 256 + col]     = c0;
            s_corr[(m0 + g)     * 256 + col + 1] = c1;
            s_corr[(m0 + g + 8) * 256 + col]     = c2;
            s_corr[(m0 + g + 8) * 256 + col + 1] = c3;
        }
    }
    __syncthreads();

    // ===== Phase C: means + attention MLP + depthwise (one tower) =====
    {
        const int p0 = warp * 4;
#pragma unroll
        for (int j = 0; j < 4; j++) {
            const int p = p0 + j;
            float ps = 0.0f;
#pragma unroll
            for (int i = 0; i < 8; i++) ps += s_corr[p * NHW + lane + 32 * i];
#pragma unroll
            for (int o = 16; o > 0; o >>= 1) ps += __shfl_xor_sync(0xffffffffu, ps, o);
            if (lane == 0) s_att[p] = ps * (1.0f / 256.0f);
        }
    }
    __syncthreads();
    if (tid < 64) {
        float s1 = ca_b1[tid];
        const float* w = ca_w1 + tid * 64;
#pragma unroll 8
        for (int j = 0; j < 64; j++) s1 = fmaf(w[j], s_att[j], s1);
        s_h[tid] = fmaxf(s1, 0.0f);
    }
    __syncthreads();
    if (tid < 64) {
        float s2 = ca_b2[tid];
        const float* w = ca_w2 + tid * 64;
#pragma unroll 8
        for (int j = 0; j < 64; j++) s2 = fmaf(w[j], s_h[j], s2);
        s_a[tid] = 1.0f / (1.0f + expf(-s2));
    }
    __syncthreads();

    {
        const int px = tid & 255, ph = tid >> 8;   // 2 p-halves
        const int y = px >> 4, x = px & 15;
        const bool okU = y > 0, okD = y < 15, okL = x > 0, okR = x < 15;
        __half* dw16 = (__half*)(sm + SM_DW);
#pragma unroll 2
        for (int pi = 0; pi < 32; pi++) {
            const int p = ph * 32 + pi;
            const float* r = s_corr + p * NHW + px;
            float nv[9];
            nv[4] = r[0];
            nv[1] = okU ? r[-16] : 0.0f;
            nv[0] = (okU && okL) ? r[-17] : 0.0f;
            nv[2] = (okU && okR) ? r[-15] : 0.0f;
            nv[7] = okD ? r[16] : 0.0f;
            nv[6] = (okD && okL) ? r[15] : 0.0f;
            nv[8] = (okD && okR) ? r[17] : 0.0f;
            nv[3] = okL ? r[-1] : 0.0f;
            nv[5] = okR ? r[1] : 0.0f;
            const float* w = sm + SM_DWW + p * 9;
            float ac = 0.0f;
#pragma unroll
            for (int k = 0; k < 9; k++) ac = fmaf(nv[k], w[k], ac);
            dw16[p * 264 + px] = __float2half_rn(ac * s_a[p]);
        }
    }
    __syncthreads();

    // ===== Phase D..H: tower pipeline (pwt/A_tap stage -> GEMM -> tap, x2) =====
    u32* pd = (u32*)(sm + SM_PWT);
    u32* ad = (u32*)(sm + SM_WP);
    float* P = sm + SM_CORR;   // corr dead after dw

    // stage pass-0 pwt + A_tap
#pragma unroll
    for (int j = 0; j < 8; j++) {
        int i = tid + j * NT;
        int o = i >> 5, kp = i & 31;
        const float* wsrc = pwW + o * 64 + 2 * kp;
        __half2 hv = __floats2half2_rn(wsrc[0], wsrc[1]);
        pd[o * 36 + kp] = *(u32*)&hv;
    }
    if (t == 1) {
        for (int i = tid; i < 48 * 64; i += NT) {
            int r = i >> 6, cp = i & 63;
            float v0 = 0.0f, v1 = 0.0f;
            if (r < 36) {
                int k = r >> 2, oc = r & 3;
                const float* wsrc = predW + oc * 2304 + k;
                v0 = wsrc[(2 * cp) * 9];
                v1 = wsrc[(2 * cp + 1) * 9];
            }
            __half2 hv = __floats2half2_rn(v0, v1);
            ad[r * 68 + cp] = *(u32*)&hv;
        }
    } else {
        for (int i = tid; i < 16 * 64; i += NT) {
            int r = i >> 6, cp = i & 63;
            float v0 = 0.0f, v1 = 0.0f;
            if (r < 9) {
                v0 = predW[(2 * cp) * 9 + r];
                v1 = predW[(2 * cp + 1) * 9 + r];
            }
            __half2 hv = __floats2half2_rn(v0, v1);
            ad[r * 68 + cp] = *(u32*)&hv;
        }
    }
    __syncthreads();

    // prefetch pass-1 pwt (hidden under GEMM0)
    float pwf0[8], pwf1[8];
#pragma unroll
    for (int j = 0; j < 8; j++) {
        int i = tid + j * NT;
        int o = i >> 5, kp = i & 31;
        const float* wsrc = pwW + (128 + o) * 64 + 2 * kp;
        pwf0[j] = wsrc[0];
        pwf1[j] = wsrc[1];
    }

    gemm_mma(sm, lane, warp, 0);
    __syncthreads();

    // STS prefetched pwt (pass 1), then tap pass 0
#pragma unroll
    for (int j = 0; j < 8; j++) {
        int i = tid + j * NT;
        int o = i >> 5, kp = i & 31;
        __half2 hv = __floats2half2_rn(pwf0[j], pwf1[j]);
        pd[o * 36 + kp] = *(u32*)&hv;
    }
    if (t == 1) {
        if (warp < 12) tap_mma<8>(sm, lane, warp >> 2, warp & 3, P, false);
    } else {
        if (warp < 8)  tap_mma<4>(sm, lane, 0, warp, P, false);
    }
    __syncthreads();

    // stage pass-1 A_tap, GEMM pass 1
    if (t == 1) {
        for (int i = tid; i < 48 * 64; i += NT) {
            int r = i >> 6, cp = i & 63;
            float v0 = 0.0f, v1 = 0.0f;
            if (r < 36) {
                int k = r >> 2, oc = r & 3;
                const float* wsrc = predW + oc * 2304 + k;
                v0 = wsrc[(128 + 2 * cp) * 9];
                v1 = wsrc[(128 + 2 * cp + 1) * 9];
            }
            __half2 hv = __floats2half2_rn(v0, v1);
            ad[r * 68 + cp] = *(u32*)&hv;
        }
    } else {
        for (int i = tid; i < 16 * 64; i += NT) {
            int r = i >> 6, cp = i & 63;
            float v0 = 0.0f, v1 = 0.0f;
            if (r < 9) {
                v0 = predW[(128 + 2 * cp) * 9 + r];
                v1 = predW[(128 + 2 * cp + 1) * 9 + r];
            }
            __half2 hv = __floats2half2_rn(v0, v1);
            ad[r * 68 + cp] = *(u32*)&hv;
        }
    }
    gemm_mma(sm, lane, warp, 128);
    __syncthreads();

    // tap pass 1 (accumulate)
    if (t == 1) {
        if (warp < 12) tap_mma<8>(sm, lane, warp >> 2, warp & 3, P, true);
    } else {
        if (warp < 8)  tap_mma<4>(sm, lane, 0, warp, P, true);
    }
    __syncthreads();

    // ===== epilogue =====
    if (tid < 256) {
        const int qx = tid, y = qx >> 4, x = qx & 15;
        if (t == 0) {
            float acc = 0.0f;
#pragma unroll
            for (int dy = -1; dy <= 1; dy++) {
                if (y + dy < 0 || y + dy > 15) continue;
#pragma unroll
                for (int dx = -1; dx <= 1; dx++) {
                    if (x + dx < 0 || x + dx > 15) continue;
                    const int k = (dy + 1) * 3 + (dx + 1);
                    acc += P[k * 256 + qx + dy * 16 + dx];
                }
            }
            out[(size_t)NB * 4 * NHW + (size_t)s * NHW + qx] =
                0.1f * (acc + cls_predb[0]);
        } else {
            float bx0 = 0.f, bx1 = 0.f, bx2 = 0.f, bx3 = 0.f;
#pragma unroll
            for (int dy = -1; dy <= 1; dy++) {
                if (y + dy < 0 || y + dy > 15) continue;
#pragma unroll
                for (int dx = -1; dx <= 1; dx++) {
                    if (x + dx < 0 || x + dx > 15) continue;
                    const int k = (dy + 1) * 3 + (dx + 1);
                    const int q = qx + dy * 16 + dx;
                    bx0 += P[(k * 4 + 0) * 256 + q];
                    bx1 += P[(k * 4 + 1) * 256 + q];
                    bx2 += P[(k * 4 + 2) * 256 + q];
                    bx3 += P[(k * 4 + 3) * 256 + q];
                }
            }
            const float adj = adjust[0];
            out[((size_t)s * 4 + 0) * NHW + qx] = expf(adj * (bx0 + box_predb[0]) + biasp[0]);
            out[((size_t)s * 4 + 1) * NHW + qx] = expf(adj * (bx1 + box_predb[1]) + biasp[1]);
            out[((size_t)s * 4 + 2) * NHW + qx] = expf(adj * (bx2 + box_predb[2]) + biasp[2]);
            out[((size_t)s * 4 + 3) * NHW + qx] = expf(adj * (bx3 + box_predb[3]) + biasp[3]);
        }
    }
}

extern "C" void kernel_launch(void* const* d_in, const int* in_sizes, int n_in,
                              void* d_out, int out_size)
{
    const float* search    = (const float*)d_in[0];
    const float* kern      = (const float*)d_in[1];
    const float* ca_w1     = (const float*)d_in[2];
    const float* ca_b1     = (const float*)d_in[3];
    const float* ca_w2     = (const float*)d_in[4];
    const float* ca_b2     = (const float*)d_in[5];
    const float* cls_dw    = (const float*)d_in[6];
    const float* cls_pw    = (const float*)d_in[7];
    const float* cls_bng   = (const float*)d_in[8];
    const float* cls_bnb   = (const float*)d_in[9];
    const float* cls_bnm   = (const float*)d_in[10];
    const float* cls_bnv   = (const float*)d_in[11];
    const float* cls_predw = (const float*)d_in[12];
    const float* cls_predb = (const float*)d_in[13];
    const float* box_dw    = (const float*)d_in[14];
    const float* box_pw    = (const float*)d_in[15];
    const float* box_bng   = (const float*)d_in[16];
    const float* box_bnb   = (const float*)d_in[17];
    const float* box_bnm   = (const float*)d_in[18];
    const float* box_bnv   = (const float*)d_in[19];
    const float* box_predw = (const float*)d_in[20];
    const float* box_predb = (const float*)d_in[21];
    const float* adjust    = (const float*)d_in[22];
    const float* biasp     = (const float*)d_in[23];

    const int smbytes = SM_TOT * 4;   // 211200 B
    cudaFuncSetAttribute(btl_fused, cudaFuncAttributeMaxDynamicSharedMemorySize, smbytes);

    btl_fused<<<NB * 2, NT, smbytes>>>(
        search, kern, ca_w1, ca_b1, ca_w2, ca_b2,
        cls_dw, cls_pw, cls_bng, cls_bnb, cls_bnm, cls_bnv, cls_predw, cls_predb,
        box_dw, box_pw, box_bng, box_bnb, box_bnm, box_bnv, box_predw, box_predb,
        adjust, biasp, (float*)d_out);
}

// round 17
// speedup vs baseline: 1.2883x; 1.2883x over previous
#include <cuda_runtime.h>
#include <cuda_fp16.h>
#include <math.h>

#define NB   512
#define NC   112
#define NP   64
#define NHW  256
#define NOC  256
#define NT1  1024   // K1 threads (32 warps)
#define K2NT 512    // K2 threads (16 warps)

typedef unsigned long long u64;
typedef unsigned int u32;

__device__ __forceinline__ u32 saddr(const void* p) {
    return (u32)__cvta_generic_to_shared(p);
}

// dw scratch: [sample][tower][p 64][px 256] fp16
__device__ __half g_dw[(size_t)NB * 2 * NP * NHW];

// ======================= KERNEL 1 (identical to R15) =======================
#define K1_ATT  0
#define K1_H    64
#define K1_A    128
#define K1_DWC  192
#define K1_DWB  768
#define K1_AZ   1344    // z fp16 [64 p][120 h] (240B rows)
#define K1_BS   5184    // search fp16 [112 c][264 h] (528B rows)
#define K1_CORR 19968   // corr fp32 [64][256]
#define K1_TOT  36352   // 145408 B

__global__ void __launch_bounds__(NT1, 1)
btl_k1(const float* __restrict__ search, const float* __restrict__ kern,
       const float* __restrict__ ca_w1, const float* __restrict__ ca_b1,
       const float* __restrict__ ca_w2, const float* __restrict__ ca_b2,
       const float* __restrict__ cls_dw, const float* __restrict__ box_dw)
{
    extern __shared__ float sm[];
    const int tid  = threadIdx.x;
    const int lane = tid & 31;
    const int warp = tid >> 5;
    const int b    = blockIdx.x;

    float* s_att  = sm + K1_ATT;
    float* s_h    = sm + K1_H;
    float* s_a    = sm + K1_A;
    float* s_corr = sm + K1_CORR;

    const float* gS = search + (size_t)b * NC * NHW;
    const float* gZ = kern   + (size_t)b * NC * NP;

    {
        u32* bd = (u32*)(sm + K1_BS);
        const float4* src = (const float4*)gS;
#pragma unroll
        for (int j = 0; j < 7; j++) {
            int i = tid + j * NT1;
            int c = i >> 6, col4 = i & 63;
            float4 v = src[i];
            __half2 h0 = __floats2half2_rn(v.x, v.y);
            __half2 h1 = __floats2half2_rn(v.z, v.w);
            bd[c * 132 + col4 * 2]     = *(u32*)&h0;
            bd[c * 132 + col4 * 2 + 1] = *(u32*)&h1;
        }
    }
    {
        __half* ad = (__half*)(sm + K1_AZ);
#pragma unroll
        for (int j = 0; j < 7; j++) {
            int i = tid + j * NT1;
            int p = i & 63, c = i >> 6;
            ad[p * 120 + c] = __float2half_rn(gZ[c * 64 + p]);
        }
    }
    for (int i = tid; i < NP * 9; i += NT1) {
        sm[K1_DWC + i] = cls_dw[i];
        sm[K1_DWB + i] = box_dw[i];
    }
    __syncthreads();

    {
        const int mt = warp >> 3, ne = warp & 7;
        const int m0 = mt * 16;
        const int g  = lane >> 2, t4 = lane & 3;

        u32 A[7][4];
        const u32 abase = saddr(sm + K1_AZ)
            + (u32)(m0 + (lane & 15)) * 240u + (u32)((lane >> 4) & 1) * 16u;
#pragma unroll
        for (int ks = 0; ks < 7; ks++) {
            asm volatile("ldmatrix.sync.aligned.m8n8.x4.shared.b16 {%0,%1,%2,%3}, [%4];"
                : "=r"(A[ks][0]), "=r"(A[ks][1]), "=r"(A[ks][2]), "=r"(A[ks][3])
                : "r"(abase + (u32)ks * 32u));
        }
        const u32 bbase = saddr(sm + K1_BS)
            + (u32)(lane & 15) * 528u + (u32)ne * 64u;
#pragma unroll
        for (int nt = 0; nt < 4; nt++) {
            float c0 = 0.f, c1 = 0.f, c2 = 0.f, c3 = 0.f;
#pragma unroll
            for (int ks = 0; ks < 7; ks++) {
                u32 b0, b1;
                asm volatile("ldmatrix.sync.aligned.m8n8.x2.trans.shared.b16 {%0,%1}, [%2];"
                    : "=r"(b0), "=r"(b1)
                    : "r"(bbase + (u32)ks * 8448u + (u32)nt * 16u));
                asm volatile(
                    "mma.sync.aligned.m16n8k16.row.col.f32.f16.f16.f32 "
                    "{%0,%1,%2,%3}, {%4,%5,%6,%7}, {%8,%9}, {%0,%1,%2,%3};"
                    : "+f"(c0), "+f"(c1), "+f"(c2), "+f"(c3)
                    : "r"(A[ks][0]), "r"(A[ks][1]), "r"(A[ks][2]), "r"(A[ks][3]),
                      "r"(b0), "r"(b1));
            }
            const int col = ne * 32 + nt * 8 + 2 * t4;
            s_corr[(m0 + g)     * 256 + col]     = c0;
            s_corr[(m0 + g)     * 256 + col + 1] = c1;
            s_corr[(m0 + g + 8) * 256 + col]     = c2;
            s_corr[(m0 + g + 8) * 256 + col + 1] = c3;
        }
    }
    __syncthreads();

    {
        const int p0 = warp * 2;
#pragma unroll
        for (int j = 0; j < 2; j++) {
            const int p = p0 + j;
            float ps = 0.0f;
#pragma unroll
            for (int i = 0; i < 8; i++) ps += s_corr[p * NHW + lane + 32 * i];
#pragma unroll
            for (int o = 16; o > 0; o >>= 1) ps += __shfl_xor_sync(0xffffffffu, ps, o);
            if (lane == 0) s_att[p] = ps * (1.0f / 256.0f);
        }
    }
    __syncthreads();

    if (tid < 64) {
        float s1 = ca_b1[tid];
        const float* w = ca_w1 + tid * 64;
#pragma unroll 8
        for (int j = 0; j < 64; j++) s1 = fmaf(w[j], s_att[j], s1);
        s_h[tid] = fmaxf(s1, 0.0f);
    }
    __syncthreads();
    if (tid < 64) {
        float s2 = ca_b2[tid];
        const float* w = ca_w2 + tid * 64;
#pragma unroll 8
        for (int j = 0; j < 64; j++) s2 = fmaf(w[j], s_h[j], s2);
        s_a[tid] = 1.0f / (1.0f + expf(-s2));
    }
    __syncthreads();

    {
        const int px = tid & 255, pq = tid >> 8;
        const int y = px >> 4, x = px & 15;
        const bool okU = y > 0, okD = y < 15, okL = x > 0, okR = x < 15;
        __half* dc = g_dw + ((size_t)b * 2)     * (NP * NHW) + px;
        __half* db = g_dw + ((size_t)b * 2 + 1) * (NP * NHW) + px;
#pragma unroll 2
        for (int pi = 0; pi < 16; pi++) {
            const int p = pq * 16 + pi;
            const float* r = s_corr + p * NHW + px;
            float nv[9];
            nv[4] = r[0];
            nv[1] = okU ? r[-16] : 0.0f;
            nv[0] = (okU && okL) ? r[-17] : 0.0f;
            nv[2] = (okU && okR) ? r[-15] : 0.0f;
            nv[7] = okD ? r[16] : 0.0f;
            nv[6] = (okD && okL) ? r[15] : 0.0f;
            nv[8] = (okD && okR) ? r[17] : 0.0f;
            nv[3] = okL ? r[-1] : 0.0f;
            nv[5] = okR ? r[1] : 0.0f;
            const float* wc = sm + K1_DWC + p * 9;
            const float* wb = sm + K1_DWB + p * 9;
            float ac = 0.0f, ab = 0.0f;
#pragma unroll
            for (int k = 0; k < 9; k++) {
                ac = fmaf(nv[k], wc[k], ac);
                ab = fmaf(nv[k], wb[k], ab);
            }
            const float a = s_a[p];
            dc[p * NHW] = __float2half_rn(ac * a);
            db[p * NHW] = __float2half_rn(ab * a);
        }
    }
}

// ======================= KERNEL 2 =======================
#define K2_BNSC 0
#define K2_BNSH 256
#define K2_WP   512     // A_tap fp16: box [48][68 u32], cls [16][68 u32]
#define K2_DW   5632    // dw fp16 [64][132 u32] (528B rows)
#define K2_PWT  14080   // pwt fp16 [128][36 u32]
#define K2_FT   18688   // ft fp16 [128][132 u32]
#define K2_PB   35584   // P: box [48][256] f32, cls [16][256] f32
#define K2_TOT  47872   // 191488 B

__device__ __forceinline__ void gemm_mma(float* sm, int lane, int warp, int o_base)
{
    const u32 pwt_b = saddr(sm + K2_PWT);
    const u32 dw_b  = saddr(sm + K2_DW);
    u32* s_ft = (u32*)(sm + K2_FT);
    const float* s_bnsc = sm + K2_BNSC;
    const float* s_bnsh = sm + K2_BNSH;

    const int mt = warp >> 1, h = warp & 1;
    const int m0 = mt * 16;
    const int g  = lane >> 2, t4 = lane & 3;

    u32 A[4][4];
    {
        const u32 aoff = pwt_b
            + (u32)(m0 + (lane & 7) + ((lane >> 3) & 1) * 8) * 144u
            + (u32)((lane >> 4) & 1) * 16u;
#pragma unroll
        for (int ks = 0; ks < 4; ks++) {
            asm volatile("ldmatrix.sync.aligned.m8n8.x4.shared.b16 {%0,%1,%2,%3}, [%4];"
                : "=r"(A[ks][0]), "=r"(A[ks][1]), "=r"(A[ks][2]), "=r"(A[ks][3])
                : "r"(aoff + (u32)ks * 32u));
        }
    }

    const float sc0 = s_bnsc[o_base + m0 + g],     sh0 = s_bnsh[o_base + m0 + g];
    const float sc1 = s_bnsc[o_base + m0 + g + 8], sh1 = s_bnsh[o_base + m0 + g + 8];
    const u32 boff = dw_b + (u32)(lane & 15) * 528u + (u32)h * 256u;

#pragma unroll 4
    for (int nt = 0; nt < 16; nt++) {
        float c0 = 0.f, c1 = 0.f, c2 = 0.f, c3 = 0.f;
#pragma unroll
        for (int ks = 0; ks < 4; ks++) {
            u32 b0, b1;
            asm volatile("ldmatrix.sync.aligned.m8n8.x2.trans.shared.b16 {%0,%1}, [%2];"
                : "=r"(b0), "=r"(b1)
                : "r"(boff + (u32)ks * 8448u + (u32)nt * 16u));
            asm volatile(
                "mma.sync.aligned.m16n8k16.row.col.f32.f16.f16.f32 "
                "{%0,%1,%2,%3}, {%4,%5,%6,%7}, {%8,%9}, {%0,%1,%2,%3};"
                : "+f"(c0), "+f"(c1), "+f"(c2), "+f"(c3)
                : "r"(A[ks][0]), "r"(A[ks][1]), "r"(A[ks][2]), "r"(A[ks][3]),
                  "r"(b0), "r"(b1));
        }
        c0 = fmaxf(fmaf(c0, sc0, sh0), 0.0f);
        c1 = fmaxf(fmaf(c1, sc0, sh0), 0.0f);
        c2 = fmaxf(fmaf(c2, sc1, sh1), 0.0f);
        c3 = fmaxf(fmaf(c3, sc1, sh1), 0.0f);
        __half2 p01 = __floats2half2_rn(c0, c1);
        __half2 p23 = __floats2half2_rn(c2, c3);
        const int n0h = h * 64 + nt * 4;
        s_ft[(m0 + g)     * 132 + n0h + t4] = *(u32*)&p01;
        s_ft[(m0 + g + 8) * 132 + n0h + t4] = *(u32*)&p23;
    }
}

template<int NT_I>
__device__ __forceinline__ void tap_mma(float* sm, int lane, int mt, int nq,
                                        float* P, bool accum)
{
    const int m0 = mt * 16;
    const int g = lane >> 2, t4 = lane & 3;
    const u32 aoff = saddr(sm + K2_WP)
        + (u32)(m0 + (lane & 15)) * 272u
        + (u32)((lane >> 4) & 1) * 16u;
    const u32 boff = saddr(sm + K2_FT)
        + (u32)(lane & 15) * 528u + (u32)(nq * NT_I * 16);

    float acc[NT_I][4];
#pragma unroll
    for (int nt = 0; nt < NT_I; nt++)
#pragma unroll
        for (int e = 0; e < 4; e++) acc[nt][e] = 0.f;

#pragma unroll
    for (int ks = 0; ks < 8; ks++) {
        u32 A0, A1, A2, A3;
        asm volatile("ldmatrix.sync.aligned.m8n8.x4.shared.b16 {%0,%1,%2,%3}, [%4];"
            : "=r"(A0), "=r"(A1), "=r"(A2), "=r"(A3)
            : "r"(aoff + (u32)ks * 32u));
#pragma unroll
        for (int nt = 0; nt < NT_I; nt++) {
            u32 b0, b1;
            asm volatile("ldmatrix.sync.aligned.m8n8.x2.trans.shared.b16 {%0,%1}, [%2];"
                : "=r"(b0), "=r"(b1)
                : "r"(boff + (u32)ks * 8448u + (u32)nt * 16u));
            asm volatile(
                "mma.sync.aligned.m16n8k16.row.col.f32.f16.f16.f32 "
                "{%0,%1,%2,%3}, {%4,%5,%6,%7}, {%8,%9}, {%0,%1,%2,%3};"
                : "+f"(acc[nt][0]), "+f"(acc[nt][1]),
                  "+f"(acc[nt][2]), "+f"(acc[nt][3])
                : "r"(A0), "r"(A1), "r"(A2), "r"(A3), "r"(b0), "r"(b1));
        }
    }

#pragma unroll
    for (int nt = 0; nt < NT_I; nt++) {
        const int col = nq * (NT_I * 8) + nt * 8 + 2 * t4;
        const int r0 = m0 + g, r1 = m0 + g + 8;
        if (!accum) {
            P[r0 * 256 + col]     = acc[nt][0];
            P[r0 * 256 + col + 1] = acc[nt][1];
            P[r1 * 256 + col]     = acc[nt][2];
            P[r1 * 256 + col + 1] = acc[nt][3];
        } else {
            P[r0 * 256 + col]     += acc[nt][0];
            P[r0 * 256 + col + 1] += acc[nt][1];
            P[r1 * 256 + col]     += acc[nt][2];
            P[r1 * 256 + col + 1] += acc[nt][3];
        }
    }
}

__global__ void __launch_bounds__(K2NT, 1)
btl_k2(const float* __restrict__ cls_pw,
       const float* __restrict__ cls_bng, const float* __restrict__ cls_bnb,
       const float* __restrict__ cls_bnm, const float* __restrict__ cls_bnv,
       const float* __restrict__ cls_predw, const float* __restrict__ cls_predb,
       const float* __restrict__ box_pw,
       const float* __restrict__ box_bng, const float* __restrict__ box_bnb,
       const float* __restrict__ box_bnm, const float* __restrict__ box_bnv,
       const float* __restrict__ box_predw, const float* __restrict__ box_predb,
       const float* __restrict__ adjust, const float* __restrict__ biasp,
       float* __restrict__ out)
{
    extern __shared__ float sm[];
    const int tid  = threadIdx.x;
    const int lane = tid & 31;
    const int warp = tid >> 5;
    const int s    = blockIdx.x >> 1;
    const int t    = blockIdx.x & 1;

    // ---- dw staging via cp.async (overlaps with weight staging below) ----
    {
        const char* src = (const char*)(g_dw + ((size_t)s * 2 + t) * (NP * NHW));
        const u32 dstb = saddr(sm + K2_DW);
#pragma unroll
        for (int j = 0; j < 4; j++) {
            int i = tid + j * K2NT;            // 0..2047 16B chunks
            int row = i >> 5, ch = i & 31;
            u32 d = dstb + (u32)(row * 528 + ch * 16);
            asm volatile("cp.async.cg.shared.global [%0], [%1], 16;"
                         :: "r"(d), "l"(src + (size_t)i * 16) : "memory");
        }
        asm volatile("cp.async.commit_group;");
    }
    if (tid < NOC) {
        const float* bng = t ? box_bng : cls_bng;
        const float* bnb = t ? box_bnb : cls_bnb;
        const float* bnm = t ? box_bnm : cls_bnm;
        const float* bnv = t ? box_bnv : cls_bnv;
        float sc = bng[tid] * rsqrtf(bnv[tid] + 1e-5f);
        sm[K2_BNSC + tid] = sc;
        sm[K2_BNSH + tid] = bnb[tid] - bnm[tid] * sc;
    }

    const float* pwW = t ? box_pw : cls_pw;
    const float* predW = t ? box_predw : cls_predw;
    u32* pd = (u32*)(sm + K2_PWT);
    u32* ad = (u32*)(sm + K2_WP);
    float* P = sm + K2_PB;

    // ---- stage pass-0 pwt + A_tap ----
#pragma unroll
    for (int j = 0; j < 8; j++) {
        int i = tid + j * K2NT;
        int o = i >> 5, kp = i & 31;
        const float* wsrc = pwW + o * 64 + 2 * kp;
        __half2 hv = __floats2half2_rn(wsrc[0], wsrc[1]);
        pd[o * 36 + kp] = *(u32*)&hv;
    }
    if (t == 1) {
        for (int i = tid; i < 48 * 64; i += K2NT) {
            int r = i >> 6, cp = i & 63;
            float v0 = 0.0f, v1 = 0.0f;
            if (r < 36) {
                int k = r >> 2, oc = r & 3;
                const float* wsrc = predW + oc * 2304 + k;
                v0 = wsrc[(2 * cp) * 9];
                v1 = wsrc[(2 * cp + 1) * 9];
            }
            __half2 hv = __floats2half2_rn(v0, v1);
            ad[r * 68 + cp] = *(u32*)&hv;
        }
    } else {
        for (int i = tid; i < 16 * 64; i += K2NT) {
            int r = i >> 6, cp = i & 63;
            float v0 = 0.0f, v1 = 0.0f;
            if (r < 9) {
                v0 = predW[(2 * cp) * 9 + r];
                v1 = predW[(2 * cp + 1) * 9 + r];
            }
            __half2 hv = __floats2half2_rn(v0, v1);
            ad[r * 68 + cp] = *(u32*)&hv;
        }
    }
    asm volatile("cp.async.wait_group 0;" ::: "memory");
    __syncthreads();

    // ---- prefetch pass-1 pwt into registers (hidden under GEMM0) ----
    float pwf0[8], pwf1[8];
#pragma unroll
    for (int j = 0; j < 8; j++) {
        int i = tid + j * K2NT;
        int o = i >> 5, kp = i & 31;
        const float* wsrc = pwW + (128 + o) * 64 + 2 * kp;
        pwf0[j] = wsrc[0];
        pwf1[j] = wsrc[1];
    }

    gemm_mma(sm, lane, warp, 0);
    __syncthreads();

    // ---- STS prefetched pwt (pass 1); prefetch pass-1 A_tap; tap pass 0 ----
#pragma unroll
    for (int j = 0; j < 8; j++) {
        int i = tid + j * K2NT;
        int o = i >> 5, kp = i & 31;
        __half2 hv = __floats2half2_rn(pwf0[j], pwf1[j]);
        pd[o * 36 + kp] = *(u32*)&hv;
    }
    float av0[6], av1[6];
#pragma unroll
    for (int j = 0; j < 6; j++) { av0[j] = 0.0f; av1[j] = 0.0f; }
    if (t == 1) {
#pragma unroll
        for (int j = 0; j < 6; j++) {
            int i = tid + j * K2NT;
            int r = i >> 6, cp = i & 63;
            if (r < 36) {
                int k = r >> 2, oc = r & 3;
                const float* wsrc = predW + oc * 2304 + k;
                av0[j] = wsrc[(128 + 2 * cp) * 9];
                av1[j] = wsrc[(128 + 2 * cp + 1) * 9];
            }
        }
        if (warp < 12) tap_mma<8>(sm, lane, warp >> 2, warp & 3, P, false);
    } else {
#pragma unroll
        for (int j = 0; j < 2; j++) {
            int i = tid + j * K2NT;
            int r = i >> 6, cp = i & 63;
            if (r < 9) {
                av0[j] = predW[(128 + 2 * cp) * 9 + r];
                av1[j] = predW[(128 + 2 * cp + 1) * 9 + r];
            }
        }
        if (warp < 8)  tap_mma<4>(sm, lane, 0, warp, P, false);
    }
    __syncthreads();

    // ---- STS prefetched pass-1 A_tap, GEMM pass 1 ----
    if (t == 1) {
#pragma unroll
        for (int j = 0; j < 6; j++) {
            int i = tid + j * K2NT;
            int r = i >> 6, cp = i & 63;
            __half2 hv = __floats2half2_rn(av0[j], av1[j]);
            ad[r * 68 + cp] = *(u32*)&hv;
        }
    } else {
#pragma unroll
        for (int j = 0; j < 2; j++) {
            int i = tid + j * K2NT;
            int r = i >> 6, cp = i & 63;
            __half2 hv = __floats2half2_rn(av0[j], av1[j]);
            ad[r * 68 + cp] = *(u32*)&hv;
        }
    }
    gemm_mma(sm, lane, warp, 128);
    __syncthreads();

    // ---- tap pass 1 (accumulate) ----
    if (t == 1) {
        if (warp < 12) tap_mma<8>(sm, lane, warp >> 2, warp & 3, P, true);
    } else {
        if (warp < 8)  tap_mma<4>(sm, lane, 0, warp, P, true);
    }
    __syncthreads();

    // ---- epilogue ----
    if (tid < 256) {
        const int qx = tid, y = qx >> 4, x = qx & 15;
        if (t == 0) {
            float acc = 0.0f;
#pragma unroll
            for (int dy = -1; dy <= 1; dy++) {
                if (y + dy < 0 || y + dy > 15) continue;
#pragma unroll
                for (int dx = -1; dx <= 1; dx++) {
                    if (x + dx < 0 || x + dx > 15) continue;
                    const int k = (dy + 1) * 3 + (dx + 1);
                    acc += P[k * 256 + qx + dy * 16 + dx];
                }
            }
            out[(size_t)NB * 4 * NHW + (size_t)s * NHW + qx] =
                0.1f * (acc + cls_predb[0]);
        } else {
            float bx0 = 0.f, bx1 = 0.f, bx2 = 0.f, bx3 = 0.f;
#pragma unroll
            for (int dy = -1; dy <= 1; dy++) {
                if (y + dy < 0 || y + dy > 15) continue;
#pragma unroll
                for (int dx = -1; dx <= 1; dx++) {
                    if (x + dx < 0 || x + dx > 15) continue;
                    const int k = (dy + 1) * 3 + (dx + 1);
                    const int q = qx + dy * 16 + dx;
                    bx0 += P[(k * 4 + 0) * 256 + q];
                    bx1 += P[(k * 4 + 1) * 256 + q];
                    bx2 += P[(k * 4 + 2) * 256 + q];
                    bx3 += P[(k * 4 + 3) * 256 + q];
                }
            }
            const float adj = adjust[0];
            out[((size_t)s * 4 + 0) * NHW + qx] = expf(adj * (bx0 + box_predb[0]) + biasp[0]);
            out[((size_t)s * 4 + 1) * NHW + qx] = expf(adj * (bx1 + box_predb[1]) + biasp[1]);
            out[((size_t)s * 4 + 2) * NHW + qx] = expf(adj * (bx2 + box_predb[2]) + biasp[2]);
            out[((size_t)s * 4 + 3) * NHW + qx] = expf(adj * (bx3 + box_predb[3]) + biasp[3]);
        }
    }
}

extern "C" void kernel_launch(void* const* d_in, const int* in_sizes, int n_in,
                              void* d_out, int out_size)
{
    const float* search    = (const float*)d_in[0];
    const float* kern      = (const float*)d_in[1];
    const float* ca_w1     = (const float*)d_in[2];
    const float* ca_b1     = (const float*)d_in[3];
    const float* ca_w2     = (const float*)d_in[4];
    const float* ca_b2     = (const float*)d_in[5];
    const float* cls_dw    = (const float*)d_in[6];
    const float* cls_pw    = (const float*)d_in[7];
    const float* cls_bng   = (const float*)d_in[8];
    const float* cls_bnb   = (const float*)d_in[9];
    const float* cls_bnm   = (const float*)d_in[10];
    const float* cls_bnv   = (const float*)d_in[11];
    const float* cls_predw = (const float*)d_in[12];
    const float* cls_predb = (const float*)d_in[13];
    const float* box_dw    = (const float*)d_in[14];
    const float* box_pw    = (const float*)d_in[15];
    const float* box_bng   = (const float*)d_in[16];
    const float* box_bnb   = (const float*)d_in[17];
    const float* box_bnm   = (const float*)d_in[18];
    const float* box_bnv   = (const float*)d_in[19];
    const float* box_predw = (const float*)d_in[20];
    const float* box_predb = (const float*)d_in[21];
    const float* adjust    = (const float*)d_in[22];
    const float* biasp     = (const float*)d_in[23];

    const int sm1 = K1_TOT * 4;   // 145408 B
    const int sm2 = K2_TOT * 4;   // 191488 B
    cudaFuncSetAttribute(btl_k1, cudaFuncAttributeMaxDynamicSharedMemorySize, sm1);
    cudaFuncSetAttribute(btl_k2, cudaFuncAttributeMaxDynamicSharedMemorySize, sm2);

    btl_k1<<<NB, NT1, sm1>>>(search, kern, ca_w1, ca_b1, ca_w2, ca_b2, cls_dw, box_dw);
    btl_k2<<<NB * 2, K2NT, sm2>>>(cls_pw, cls_bng, cls_bnb, cls_bnm, cls_bnv,
                                  cls_predw, cls_predb,
                                  box_pw, box_bng, box_bnb, box_bnm, box_bnv,
                                  box_predw, box_predb,
                                  adjust, biasp, (float*)d_out);
}